// round 3
// baseline (speedup 1.0000x reference)
#include <cuda_runtime.h>
#include <math.h>

#define BB 4
#define TT 2048
#define CC 1024
#define HH 16
#define HD 64

// Scratch (device globals: allocation-free per harness rules)
__device__ float g_q[(size_t)BB*HH*TT*HD];   // [B,H,T,HD]
__device__ float g_k[(size_t)BB*HH*TT*HD];
__device__ float g_v[(size_t)BB*HH*TT*HD];
__device__ float g_y[(size_t)BB*TT*CC];      // attention out, [B,T,C]

// ---------------------------------------------------------------------------
// GEMM 1: fused QKV projections.
// out[m,n] = sum_c X[m,c] * W[n,c] + bias[n], scattered into [B,H,T,HD].
// 128x128 tile, BK=16, 256 threads, 8x8 micro-tile per thread.
// ---------------------------------------------------------------------------
__global__ __launch_bounds__(256)
void qkv_gemm_kernel(const float* __restrict__ X,
                     const float* __restrict__ Wk, const float* __restrict__ bk,
                     const float* __restrict__ Wq, const float* __restrict__ bq,
                     const float* __restrict__ Wv, const float* __restrict__ bv)
{
    __shared__ float As[16][132];   // [k][m], padded row (132*4=528B, 16B-aligned)
    __shared__ float Bs[16][132];   // [k][n]

    const float* W; const float* bias; float* out;
    if (blockIdx.z == 0)      { W = Wk; bias = bk; out = g_k; }
    else if (blockIdx.z == 1) { W = Wq; bias = bq; out = g_q; }
    else                      { W = Wv; bias = bv; out = g_v; }

    const int K = CC;
    const int tid = threadIdx.x;
    const int ty = tid >> 4, tx = tid & 15;
    const int mBase = blockIdx.y << 7;
    const int nBase = blockIdx.x << 7;
    const int lr = tid >> 2;          // 0..63
    const int lc = (tid & 3) << 2;    // 0,4,8,12

    float acc[8][8];
#pragma unroll
    for (int i = 0; i < 8; i++)
#pragma unroll
        for (int j = 0; j < 8; j++) acc[i][j] = 0.f;

    const float* Ap = X + (size_t)(mBase + lr) * K + lc;
    const float* Bp = W + (size_t)(nBase + lr) * K + lc;

    for (int kb = 0; kb < K; kb += 16) {
        float4 a0 = *(const float4*)(Ap + kb);
        float4 a1 = *(const float4*)(Ap + (size_t)64 * K + kb);
        float4 b0 = *(const float4*)(Bp + kb);
        float4 b1 = *(const float4*)(Bp + (size_t)64 * K + kb);
        As[lc+0][lr]    = a0.x; As[lc+1][lr]    = a0.y; As[lc+2][lr]    = a0.z; As[lc+3][lr]    = a0.w;
        As[lc+0][lr+64] = a1.x; As[lc+1][lr+64] = a1.y; As[lc+2][lr+64] = a1.z; As[lc+3][lr+64] = a1.w;
        Bs[lc+0][lr]    = b0.x; Bs[lc+1][lr]    = b0.y; Bs[lc+2][lr]    = b0.z; Bs[lc+3][lr]    = b0.w;
        Bs[lc+0][lr+64] = b1.x; Bs[lc+1][lr+64] = b1.y; Bs[lc+2][lr+64] = b1.z; Bs[lc+3][lr+64] = b1.w;
        __syncthreads();
#pragma unroll
        for (int k = 0; k < 16; k++) {
            float a[8], b[8];
            *(float4*)(a)   = *(const float4*)&As[k][ty*8];
            *(float4*)(a+4) = *(const float4*)&As[k][ty*8+4];
            *(float4*)(b)   = *(const float4*)&Bs[k][tx*8];
            *(float4*)(b+4) = *(const float4*)&Bs[k][tx*8+4];
#pragma unroll
            for (int i = 0; i < 8; i++)
#pragma unroll
                for (int j = 0; j < 8; j++)
                    acc[i][j] = fmaf(a[i], b[j], acc[i][j]);
        }
        __syncthreads();
    }

    // Epilogue: scatter to [B,H,T,HD] with bias
#pragma unroll
    for (int i = 0; i < 8; i++) {
        int m = mBase + ty*8 + i;
        int bb = m >> 11;           // T = 2048
        int t  = m & (TT - 1);
#pragma unroll
        for (int j = 0; j < 8; j++) {
            int n = nBase + tx*8 + j;
            int h = n >> 6, d = n & 63;
            out[(((size_t)bb*HH + h)*TT + t)*HD + d] = acc[i][j] + bias[n];
        }
    }
}

// ---------------------------------------------------------------------------
// Kernel 2: causal flash attention, fp32, online softmax.
// Block: 64 q-rows x full HD; loops over k-tiles of 64 (only kt <= qt).
// 256 threads; thread (ty,tx) owns S/O rows 4ty..4ty+3, cols 4tx..4tx+3.
// Dynamic smem: Qs[64][64] | Ks[64][65] | Vs[64][64] | Ps[64][65] = 66048 B.
// ---------------------------------------------------------------------------
__global__ __launch_bounds__(256)
void flash_attn_kernel()
{
    extern __shared__ float sm[];
    float* Qs = sm;                         // 64*64
    float* Ks = sm + 64*64;                 // 64*65 (pad 65 -> conflict-free-ish)
    float* Vs = Ks + 64*65;                 // 64*64
    float* Ps = Vs + 64*64;                 // 64*65

    const int tid = threadIdx.x;
    const int ty = tid >> 4, tx = tid & 15;
    const int r0 = ty << 2, c0 = tx << 2;
    const int qt = blockIdx.x;              // q-tile (0..31)
    const int bh = blockIdx.y;              // b*H + h (0..63)

    const float* Qg = g_q + (size_t)bh * TT * HD + (size_t)qt * 64 * HD;
    const float* Kg = g_k + (size_t)bh * TT * HD;
    const float* Vg = g_v + (size_t)bh * TT * HD;

    // Load Q tile, pre-scaled by 1/sqrt(HD) = 0.125
    {
        int row = tid >> 4;                 // 0..15
        int c4  = (tid & 15) << 2;
#pragma unroll
        for (int it = 0; it < 4; it++) {
            int r = row + it*16;
            float4 v = *(const float4*)&Qg[(size_t)r*HD + c4];
            v.x *= 0.125f; v.y *= 0.125f; v.z *= 0.125f; v.w *= 0.125f;
            *(float4*)&Qs[r*64 + c4] = v;
        }
    }

    float m_i[4], l_i[4], O[4][4];
#pragma unroll
    for (int i = 0; i < 4; i++) {
        m_i[i] = -INFINITY; l_i[i] = 0.f;
#pragma unroll
        for (int j = 0; j < 4; j++) O[i][j] = 0.f;
    }

    for (int kt = 0; kt <= qt; kt++) {
        __syncthreads();   // protect smem from previous iteration's readers
        // Load K (scalar stores into padded rows) and V (float4)
        {
            int row = tid >> 4;
            int c4  = (tid & 15) << 2;
#pragma unroll
            for (int it = 0; it < 4; it++) {
                int r = row + it*16;
                size_t goff = (size_t)(kt*64 + r) * HD + c4;
                float4 kv = *(const float4*)&Kg[goff];
                Ks[r*65 + c4+0] = kv.x; Ks[r*65 + c4+1] = kv.y;
                Ks[r*65 + c4+2] = kv.z; Ks[r*65 + c4+3] = kv.w;
                float4 vv = *(const float4*)&Vg[goff];
                *(float4*)&Vs[r*64 + c4] = vv;
            }
        }
        __syncthreads();

        // S = Qs * Ks^T  (4x4 per thread)
        float S[4][4];
#pragma unroll
        for (int i = 0; i < 4; i++)
#pragma unroll
            for (int j = 0; j < 4; j++) S[i][j] = 0.f;
#pragma unroll 8
        for (int d = 0; d < 64; d++) {
            float qv[4], kv[4];
#pragma unroll
            for (int i = 0; i < 4; i++) qv[i] = Qs[(r0+i)*64 + d];
#pragma unroll
            for (int j = 0; j < 4; j++) kv[j] = Ks[(c0+j)*65 + d];
#pragma unroll
            for (int i = 0; i < 4; i++)
#pragma unroll
                for (int j = 0; j < 4; j++)
                    S[i][j] = fmaf(qv[i], kv[j], S[i][j]);
        }

        // Causal mask (only on the diagonal tile)
        if (kt == qt) {
#pragma unroll
            for (int i = 0; i < 4; i++)
#pragma unroll
                for (int j = 0; j < 4; j++)
                    if (c0 + j > r0 + i) S[i][j] = -INFINITY;
        }

        // Online softmax: rows are spread across 16 lanes (same ty)
        float mloc[4];
#pragma unroll
        for (int i = 0; i < 4; i++)
            mloc[i] = fmaxf(fmaxf(S[i][0], S[i][1]), fmaxf(S[i][2], S[i][3]));
#pragma unroll
        for (int off = 1; off < 16; off <<= 1)
#pragma unroll
            for (int i = 0; i < 4; i++)
                mloc[i] = fmaxf(mloc[i], __shfl_xor_sync(0xffffffffu, mloc[i], off));

        float corr[4], rs[4];
#pragma unroll
        for (int i = 0; i < 4; i++) {
            float mn = fmaxf(m_i[i], mloc[i]);
            corr[i] = __expf(m_i[i] - mn);   // first tile: exp(-inf) = 0
            m_i[i] = mn;
        }
#pragma unroll
        for (int i = 0; i < 4; i++) {
            float s = 0.f;
#pragma unroll
            for (int j = 0; j < 4; j++) {
                float p = __expf(S[i][j] - m_i[i]);  // masked -> exp(-inf)=0
                S[i][j] = p;
                s += p;
            }
            rs[i] = s;
        }
#pragma unroll
        for (int off = 1; off < 16; off <<= 1)
#pragma unroll
            for (int i = 0; i < 4; i++)
                rs[i] += __shfl_xor_sync(0xffffffffu, rs[i], off);
#pragma unroll
        for (int i = 0; i < 4; i++) {
            l_i[i] = l_i[i] * corr[i] + rs[i];
#pragma unroll
            for (int j = 0; j < 4; j++) O[i][j] *= corr[i];
        }

        // Stage P for the cross-thread P*V contraction
#pragma unroll
        for (int i = 0; i < 4; i++)
#pragma unroll
            for (int j = 0; j < 4; j++)
                Ps[(r0+i)*65 + c0 + j] = S[i][j];
        __syncthreads();

        // O += P * V
#pragma unroll 8
        for (int c = 0; c < 64; c++) {
            float pv[4], vv[4];
#pragma unroll
            for (int i = 0; i < 4; i++) pv[i] = Ps[(r0+i)*65 + c];
#pragma unroll
            for (int j = 0; j < 4; j++) vv[j] = Vs[c*64 + c0 + j];
#pragma unroll
            for (int i = 0; i < 4; i++)
#pragma unroll
                for (int j = 0; j < 4; j++)
                    O[i][j] = fmaf(pv[i], vv[j], O[i][j]);
        }
    }

    // Epilogue: normalize and write to [B,T,C] scratch
    const int b = bh >> 4, h = bh & 15;
#pragma unroll
    for (int i = 0; i < 4; i++) {
        float inv = 1.0f / l_i[i];
        int t = qt*64 + r0 + i;
        float* orow = g_y + ((size_t)b*TT + t)*CC + h*HD + c0;
        float4 o4;
        o4.x = O[i][0]*inv; o4.y = O[i][1]*inv; o4.z = O[i][2]*inv; o4.w = O[i][3]*inv;
        *(float4*)orow = o4;
    }
}

// ---------------------------------------------------------------------------
// GEMM 3: output projection. out[m,n] = sum_c g_y[m,c]*Wp[n,c] + bp[n]
// ---------------------------------------------------------------------------
__global__ __launch_bounds__(256)
void proj_gemm_kernel(const float* __restrict__ Wp, const float* __restrict__ bp,
                      float* __restrict__ outp)
{
    __shared__ float As[16][132];
    __shared__ float Bs[16][132];

    const int K = CC;
    const int tid = threadIdx.x;
    const int ty = tid >> 4, tx = tid & 15;
    const int mBase = blockIdx.y << 7;
    const int nBase = blockIdx.x << 7;
    const int lr = tid >> 2;
    const int lc = (tid & 3) << 2;

    float acc[8][8];
#pragma unroll
    for (int i = 0; i < 8; i++)
#pragma unroll
        for (int j = 0; j < 8; j++) acc[i][j] = 0.f;

    const float* Ap = g_y + (size_t)(mBase + lr) * K + lc;
    const float* Bp = Wp  + (size_t)(nBase + lr) * K + lc;

    for (int kb = 0; kb < K; kb += 16) {
        float4 a0 = *(const float4*)(Ap + kb);
        float4 a1 = *(const float4*)(Ap + (size_t)64 * K + kb);
        float4 b0 = *(const float4*)(Bp + kb);
        float4 b1 = *(const float4*)(Bp + (size_t)64 * K + kb);
        As[lc+0][lr]    = a0.x; As[lc+1][lr]    = a0.y; As[lc+2][lr]    = a0.z; As[lc+3][lr]    = a0.w;
        As[lc+0][lr+64] = a1.x; As[lc+1][lr+64] = a1.y; As[lc+2][lr+64] = a1.z; As[lc+3][lr+64] = a1.w;
        Bs[lc+0][lr]    = b0.x; Bs[lc+1][lr]    = b0.y; Bs[lc+2][lr]    = b0.z; Bs[lc+3][lr]    = b0.w;
        Bs[lc+0][lr+64] = b1.x; Bs[lc+1][lr+64] = b1.y; Bs[lc+2][lr+64] = b1.z; Bs[lc+3][lr+64] = b1.w;
        __syncthreads();
#pragma unroll
        for (int k = 0; k < 16; k++) {
            float a[8], b[8];
            *(float4*)(a)   = *(const float4*)&As[k][ty*8];
            *(float4*)(a+4) = *(const float4*)&As[k][ty*8+4];
            *(float4*)(b)   = *(const float4*)&Bs[k][tx*8];
            *(float4*)(b+4) = *(const float4*)&Bs[k][tx*8+4];
#pragma unroll
            for (int i = 0; i < 8; i++)
#pragma unroll
                for (int j = 0; j < 8; j++)
                    acc[i][j] = fmaf(a[i], b[j], acc[i][j]);
        }
        __syncthreads();
    }

#pragma unroll
    for (int i = 0; i < 8; i++) {
        int m = mBase + ty*8 + i;
        float* orow = outp + (size_t)m*CC + nBase + tx*8;
        float4 o0, o1;
        int n0 = nBase + tx*8;
        o0.x = acc[i][0] + bp[n0+0]; o0.y = acc[i][1] + bp[n0+1];
        o0.z = acc[i][2] + bp[n0+2]; o0.w = acc[i][3] + bp[n0+3];
        o1.x = acc[i][4] + bp[n0+4]; o1.y = acc[i][5] + bp[n0+5];
        o1.z = acc[i][6] + bp[n0+6]; o1.w = acc[i][7] + bp[n0+7];
        *(float4*)(orow)     = o0;
        *(float4*)(orow + 4) = o1;
    }
}

// ---------------------------------------------------------------------------
extern "C" void kernel_launch(void* const* d_in, const int* in_sizes, int n_in,
                              void* d_out, int out_size)
{
    const float* x  = (const float*)d_in[0];
    const float* Wk = (const float*)d_in[1];
    const float* bk = (const float*)d_in[2];
    const float* Wq = (const float*)d_in[3];
    const float* bq = (const float*)d_in[4];
    const float* Wv = (const float*)d_in[5];
    const float* bv = (const float*)d_in[6];
    const float* Wp = (const float*)d_in[7];
    const float* bp = (const float*)d_in[8];
    float* outp = (float*)d_out;

    // 66048 B dynamic smem > 48KB default: opt in (idempotent, capture-safe,
    // not a stream op, not an allocation).
    cudaFuncSetAttribute((const void*)flash_attn_kernel,
                         cudaFuncAttributeMaxDynamicSharedMemorySize, 66048);

    // QKV: M=8192, N=1024 -> grid (8, 64), z = {k,q,v}
    qkv_gemm_kernel<<<dim3(8, 64, 3), 256>>>(x, Wk, bk, Wq, bq, Wv, bv);

    // Attention: 32 q-tiles x 64 (b,h) pairs
    flash_attn_kernel<<<dim3(32, 64), 256, 66048>>>();

    // Projection: M=8192, N=1024 -> grid (8, 64)
    proj_gemm_kernel<<<dim3(8, 64), 256>>>(Wp, bp, outp);
}

// round 4
// speedup vs baseline: 1.0045x; 1.0045x over previous
#include <cuda_runtime.h>
#include <math.h>

#define BB 4
#define TT 2048
#define CC 1024
#define HH 16
#define HD 64

// Scratch (device globals: allocation-free per harness rules)
__device__ float g_q[(size_t)BB*HH*TT*HD];   // [B,H,T,HD]
__device__ float g_k[(size_t)BB*HH*TT*HD];
__device__ float g_v[(size_t)BB*HH*TT*HD];
__device__ float g_y[(size_t)BB*TT*CC];      // attention out, [B,T,C]

// ---------------------------------------------------------------------------
// GEMM 1: fused QKV projections.
// out[m,n] = sum_c X[m,c] * W[n,c] + bias[n], scattered into [B,H,T,HD].
// 128x128 tile, BK=16, 256 threads, 8x8 micro-tile per thread.
// ---------------------------------------------------------------------------
__global__ __launch_bounds__(256)
void qkv_gemm_kernel(const float* __restrict__ X,
                     const float* __restrict__ Wk, const float* __restrict__ bk,
                     const float* __restrict__ Wq, const float* __restrict__ bq,
                     const float* __restrict__ Wv, const float* __restrict__ bv)
{
    __shared__ float As[16][132];   // [k][m], padded row (132*4=528B, 16B-aligned)
    __shared__ float Bs[16][132];   // [k][n]

    const float* W; const float* bias; float* out;
    if (blockIdx.z == 0)      { W = Wk; bias = bk; out = g_k; }
    else if (blockIdx.z == 1) { W = Wq; bias = bq; out = g_q; }
    else                      { W = Wv; bias = bv; out = g_v; }

    const int K = CC;
    const int tid = threadIdx.x;
    const int ty = tid >> 4, tx = tid & 15;
    const int mBase = blockIdx.y << 7;
    const int nBase = blockIdx.x << 7;
    const int lr = tid >> 2;          // 0..63
    const int lc = (tid & 3) << 2;    // 0,4,8,12

    float acc[8][8];
#pragma unroll
    for (int i = 0; i < 8; i++)
#pragma unroll
        for (int j = 0; j < 8; j++) acc[i][j] = 0.f;

    const float* Ap = X + (size_t)(mBase + lr) * K + lc;
    const float* Bp = W + (size_t)(nBase + lr) * K + lc;

    for (int kb = 0; kb < K; kb += 16) {
        float4 a0 = *(const float4*)(Ap + kb);
        float4 a1 = *(const float4*)(Ap + (size_t)64 * K + kb);
        float4 b0 = *(const float4*)(Bp + kb);
        float4 b1 = *(const float4*)(Bp + (size_t)64 * K + kb);
        As[lc+0][lr]    = a0.x; As[lc+1][lr]    = a0.y; As[lc+2][lr]    = a0.z; As[lc+3][lr]    = a0.w;
        As[lc+0][lr+64] = a1.x; As[lc+1][lr+64] = a1.y; As[lc+2][lr+64] = a1.z; As[lc+3][lr+64] = a1.w;
        Bs[lc+0][lr]    = b0.x; Bs[lc+1][lr]    = b0.y; Bs[lc+2][lr]    = b0.z; Bs[lc+3][lr]    = b0.w;
        Bs[lc+0][lr+64] = b1.x; Bs[lc+1][lr+64] = b1.y; Bs[lc+2][lr+64] = b1.z; Bs[lc+3][lr+64] = b1.w;
        __syncthreads();
#pragma unroll
        for (int k = 0; k < 16; k++) {
            float a[8], b[8];
            *(float4*)(a)   = *(const float4*)&As[k][ty*8];
            *(float4*)(a+4) = *(const float4*)&As[k][ty*8+4];
            *(float4*)(b)   = *(const float4*)&Bs[k][tx*8];
            *(float4*)(b+4) = *(const float4*)&Bs[k][tx*8+4];
#pragma unroll
            for (int i = 0; i < 8; i++)
#pragma unroll
                for (int j = 0; j < 8; j++)
                    acc[i][j] = fmaf(a[i], b[j], acc[i][j]);
        }
        __syncthreads();
    }

    // Epilogue: scatter to [B,H,T,HD] with bias
#pragma unroll
    for (int i = 0; i < 8; i++) {
        int m = mBase + ty*8 + i;
        int bb = m >> 11;           // T = 2048
        int t  = m & (TT - 1);
#pragma unroll
        for (int j = 0; j < 8; j++) {
            int n = nBase + tx*8 + j;
            int h = n >> 6, d = n & 63;
            out[(((size_t)bb*HH + h)*TT + t)*HD + d] = acc[i][j] + bias[n];
        }
    }
}

// ---------------------------------------------------------------------------
// Kernel 2: causal flash attention, fp32, online softmax.
// Block: 64 q-rows x full HD; loops over k-tiles of 64 (only kt <= qt).
// 256 threads; thread (ty,tx) owns S/O rows 4ty..4ty+3, cols 4tx..4tx+3.
// Dynamic smem: Qs[64][64] | Ks[64][65] | Vs[64][64] | Ps[64][65] = 66048 B.
// ---------------------------------------------------------------------------
__global__ __launch_bounds__(256)
void flash_attn_kernel()
{
    extern __shared__ float sm[];
    float* Qs = sm;                         // 64*64
    float* Ks = sm + 64*64;                 // 64*65 (pad 65 -> conflict-free-ish)
    float* Vs = Ks + 64*65;                 // 64*64
    float* Ps = Vs + 64*64;                 // 64*65

    const int tid = threadIdx.x;
    const int ty = tid >> 4, tx = tid & 15;
    const int r0 = ty << 2, c0 = tx << 2;
    const int qt = blockIdx.x;              // q-tile (0..31)
    const int bh = blockIdx.y;              // b*H + h (0..63)

    const float* Qg = g_q + (size_t)bh * TT * HD + (size_t)qt * 64 * HD;
    const float* Kg = g_k + (size_t)bh * TT * HD;
    const float* Vg = g_v + (size_t)bh * TT * HD;

    // Load Q tile, pre-scaled by 1/sqrt(HD) = 0.125
    {
        int row = tid >> 4;                 // 0..15
        int c4  = (tid & 15) << 2;
#pragma unroll
        for (int it = 0; it < 4; it++) {
            int r = row + it*16;
            float4 v = *(const float4*)&Qg[(size_t)r*HD + c4];
            v.x *= 0.125f; v.y *= 0.125f; v.z *= 0.125f; v.w *= 0.125f;
            *(float4*)&Qs[r*64 + c4] = v;
        }
    }

    float m_i[4], l_i[4], O[4][4];
#pragma unroll
    for (int i = 0; i < 4; i++) {
        m_i[i] = -INFINITY; l_i[i] = 0.f;
#pragma unroll
        for (int j = 0; j < 4; j++) O[i][j] = 0.f;
    }

    for (int kt = 0; kt <= qt; kt++) {
        __syncthreads();   // protect smem from previous iteration's readers
        // Load K (scalar stores into padded rows) and V (float4)
        {
            int row = tid >> 4;
            int c4  = (tid & 15) << 2;
#pragma unroll
            for (int it = 0; it < 4; it++) {
                int r = row + it*16;
                size_t goff = (size_t)(kt*64 + r) * HD + c4;
                float4 kv = *(const float4*)&Kg[goff];
                Ks[r*65 + c4+0] = kv.x; Ks[r*65 + c4+1] = kv.y;
                Ks[r*65 + c4+2] = kv.z; Ks[r*65 + c4+3] = kv.w;
                float4 vv = *(const float4*)&Vg[goff];
                *(float4*)&Vs[r*64 + c4] = vv;
            }
        }
        __syncthreads();

        // S = Qs * Ks^T  (4x4 per thread)
        float S[4][4];
#pragma unroll
        for (int i = 0; i < 4; i++)
#pragma unroll
            for (int j = 0; j < 4; j++) S[i][j] = 0.f;
#pragma unroll 8
        for (int d = 0; d < 64; d++) {
            float qv[4], kv[4];
#pragma unroll
            for (int i = 0; i < 4; i++) qv[i] = Qs[(r0+i)*64 + d];
#pragma unroll
            for (int j = 0; j < 4; j++) kv[j] = Ks[(c0+j)*65 + d];
#pragma unroll
            for (int i = 0; i < 4; i++)
#pragma unroll
                for (int j = 0; j < 4; j++)
                    S[i][j] = fmaf(qv[i], kv[j], S[i][j]);
        }

        // Causal mask (only on the diagonal tile)
        if (kt == qt) {
#pragma unroll
            for (int i = 0; i < 4; i++)
#pragma unroll
                for (int j = 0; j < 4; j++)
                    if (c0 + j > r0 + i) S[i][j] = -INFINITY;
        }

        // Online softmax: rows are spread across 16 lanes (same ty)
        float mloc[4];
#pragma unroll
        for (int i = 0; i < 4; i++)
            mloc[i] = fmaxf(fmaxf(S[i][0], S[i][1]), fmaxf(S[i][2], S[i][3]));
#pragma unroll
        for (int off = 1; off < 16; off <<= 1)
#pragma unroll
            for (int i = 0; i < 4; i++)
                mloc[i] = fmaxf(mloc[i], __shfl_xor_sync(0xffffffffu, mloc[i], off));

        float corr[4], rs[4];
#pragma unroll
        for (int i = 0; i < 4; i++) {
            float mn = fmaxf(m_i[i], mloc[i]);
            corr[i] = __expf(m_i[i] - mn);   // first tile: exp(-inf) = 0
            m_i[i] = mn;
        }
#pragma unroll
        for (int i = 0; i < 4; i++) {
            float s = 0.f;
#pragma unroll
            for (int j = 0; j < 4; j++) {
                float p = __expf(S[i][j] - m_i[i]);  // masked -> exp(-inf)=0
                S[i][j] = p;
                s += p;
            }
            rs[i] = s;
        }
#pragma unroll
        for (int off = 1; off < 16; off <<= 1)
#pragma unroll
            for (int i = 0; i < 4; i++)
                rs[i] += __shfl_xor_sync(0xffffffffu, rs[i], off);
#pragma unroll
        for (int i = 0; i < 4; i++) {
            l_i[i] = l_i[i] * corr[i] + rs[i];
#pragma unroll
            for (int j = 0; j < 4; j++) O[i][j] *= corr[i];
        }

        // Stage P for the cross-thread P*V contraction
#pragma unroll
        for (int i = 0; i < 4; i++)
#pragma unroll
            for (int j = 0; j < 4; j++)
                Ps[(r0+i)*65 + c0 + j] = S[i][j];
        __syncthreads();

        // O += P * V
#pragma unroll 8
        for (int c = 0; c < 64; c++) {
            float pv[4], vv[4];
#pragma unroll
            for (int i = 0; i < 4; i++) pv[i] = Ps[(r0+i)*65 + c];
#pragma unroll
            for (int j = 0; j < 4; j++) vv[j] = Vs[c*64 + c0 + j];
#pragma unroll
            for (int i = 0; i < 4; i++)
#pragma unroll
                for (int j = 0; j < 4; j++)
                    O[i][j] = fmaf(pv[i], vv[j], O[i][j]);
        }
    }

    // Epilogue: normalize and write to [B,T,C] scratch
    const int b = bh >> 4, h = bh & 15;
#pragma unroll
    for (int i = 0; i < 4; i++) {
        float inv = 1.0f / l_i[i];
        int t = qt*64 + r0 + i;
        float* orow = g_y + ((size_t)b*TT + t)*CC + h*HD + c0;
        float4 o4;
        o4.x = O[i][0]*inv; o4.y = O[i][1]*inv; o4.z = O[i][2]*inv; o4.w = O[i][3]*inv;
        *(float4*)orow = o4;
    }
}

// ---------------------------------------------------------------------------
// GEMM 3: output projection. out[m,n] = sum_c g_y[m,c]*Wp[n,c] + bp[n]
// ---------------------------------------------------------------------------
__global__ __launch_bounds__(256)
void proj_gemm_kernel(const float* __restrict__ Wp, const float* __restrict__ bp,
                      float* __restrict__ outp)
{
    __shared__ float As[16][132];
    __shared__ float Bs[16][132];

    const int K = CC;
    const int tid = threadIdx.x;
    const int ty = tid >> 4, tx = tid & 15;
    const int mBase = blockIdx.y << 7;
    const int nBase = blockIdx.x << 7;
    const int lr = tid >> 2;
    const int lc = (tid & 3) << 2;

    float acc[8][8];
#pragma unroll
    for (int i = 0; i < 8; i++)
#pragma unroll
        for (int j = 0; j < 8; j++) acc[i][j] = 0.f;

    const float* Ap = g_y + (size_t)(mBase + lr) * K + lc;
    const float* Bp = Wp  + (size_t)(nBase + lr) * K + lc;

    for (int kb = 0; kb < K; kb += 16) {
        float4 a0 = *(const float4*)(Ap + kb);
        float4 a1 = *(const float4*)(Ap + (size_t)64 * K + kb);
        float4 b0 = *(const float4*)(Bp + kb);
        float4 b1 = *(const float4*)(Bp + (size_t)64 * K + kb);
        As[lc+0][lr]    = a0.x; As[lc+1][lr]    = a0.y; As[lc+2][lr]    = a0.z; As[lc+3][lr]    = a0.w;
        As[lc+0][lr+64] = a1.x; As[lc+1][lr+64] = a1.y; As[lc+2][lr+64] = a1.z; As[lc+3][lr+64] = a1.w;
        Bs[lc+0][lr]    = b0.x; Bs[lc+1][lr]    = b0.y; Bs[lc+2][lr]    = b0.z; Bs[lc+3][lr]    = b0.w;
        Bs[lc+0][lr+64] = b1.x; Bs[lc+1][lr+64] = b1.y; Bs[lc+2][lr+64] = b1.z; Bs[lc+3][lr+64] = b1.w;
        __syncthreads();
#pragma unroll
        for (int k = 0; k < 16; k++) {
            float a[8], b[8];
            *(float4*)(a)   = *(const float4*)&As[k][ty*8];
            *(float4*)(a+4) = *(const float4*)&As[k][ty*8+4];
            *(float4*)(b)   = *(const float4*)&Bs[k][tx*8];
            *(float4*)(b+4) = *(const float4*)&Bs[k][tx*8+4];
#pragma unroll
            for (int i = 0; i < 8; i++)
#pragma unroll
                for (int j = 0; j < 8; j++)
                    acc[i][j] = fmaf(a[i], b[j], acc[i][j]);
        }
        __syncthreads();
    }

#pragma unroll
    for (int i = 0; i < 8; i++) {
        int m = mBase + ty*8 + i;
        float* orow = outp + (size_t)m*CC + nBase + tx*8;
        float4 o0, o1;
        int n0 = nBase + tx*8;
        o0.x = acc[i][0] + bp[n0+0]; o0.y = acc[i][1] + bp[n0+1];
        o0.z = acc[i][2] + bp[n0+2]; o0.w = acc[i][3] + bp[n0+3];
        o1.x = acc[i][4] + bp[n0+4]; o1.y = acc[i][5] + bp[n0+5];
        o1.z = acc[i][6] + bp[n0+6]; o1.w = acc[i][7] + bp[n0+7];
        *(float4*)(orow)     = o0;
        *(float4*)(orow + 4) = o1;
    }
}

// ---------------------------------------------------------------------------
extern "C" void kernel_launch(void* const* d_in, const int* in_sizes, int n_in,
                              void* d_out, int out_size)
{
    const float* x  = (const float*)d_in[0];
    const float* Wk = (const float*)d_in[1];
    const float* bk = (const float*)d_in[2];
    const float* Wq = (const float*)d_in[3];
    const float* bq = (const float*)d_in[4];
    const float* Wv = (const float*)d_in[5];
    const float* bv = (const float*)d_in[6];
    const float* Wp = (const float*)d_in[7];
    const float* bp = (const float*)d_in[8];
    float* outp = (float*)d_out;

    // 66048 B dynamic smem > 48KB default: opt in (idempotent, capture-safe,
    // not a stream op, not an allocation).
    cudaFuncSetAttribute((const void*)flash_attn_kernel,
                         cudaFuncAttributeMaxDynamicSharedMemorySize, 66048);

    // QKV: M=8192, N=1024 -> grid (8, 64), z = {k,q,v}
    qkv_gemm_kernel<<<dim3(8, 64, 3), 256>>>(x, Wk, bk, Wq, bq, Wv, bv);

    // Attention: 32 q-tiles x 64 (b,h) pairs
    flash_attn_kernel<<<dim3(32, 64), 256, 66048>>>();

    // Projection: M=8192, N=1024 -> grid (8, 64)
    proj_gemm_kernel<<<dim3(8, 64), 256>>>(Wp, bp, outp);
}

// round 7
// speedup vs baseline: 1.5150x; 1.5083x over previous
#include <cuda_runtime.h>
#include <cuda_bf16.h>
#include <math.h>
#include <cstdint>

#define BB 4
#define TT 2048
#define CC 1024
#define HH 16
#define HD 64
#define GK 1024

// ---------------------------------------------------------------------------
// Device-global scratch (allocation-free per harness rules)
// ---------------------------------------------------------------------------
__device__ float g_q[(size_t)BB*HH*TT*HD];           // [B,H,T,HD] fp32
__device__ float g_k[(size_t)BB*HH*TT*HD];
__device__ float g_v[(size_t)BB*HH*TT*HD];
__device__ __nv_bfloat16 g_xhi[(size_t)BB*TT*CC];    // X split
__device__ __nv_bfloat16 g_xlo[(size_t)BB*TT*CC];
__device__ __nv_bfloat16 g_whi[(size_t)4*CC*CC];     // Wk,Wq,Wv,Wp split
__device__ __nv_bfloat16 g_wlo[(size_t)4*CC*CC];
__device__ __nv_bfloat16 g_yhi[(size_t)BB*TT*CC];    // attention out split
__device__ __nv_bfloat16 g_ylo[(size_t)BB*TT*CC];

// ---------------------------------------------------------------------------
// PTX helpers (sm_80+ only: mma.sync / ldmatrix / cp.async — no tcgen05)
// ---------------------------------------------------------------------------
__device__ __forceinline__ uint32_t smem_u32(const void* p) {
    uint32_t a;
    asm("{ .reg .u64 t; cvta.to.shared.u64 t, %1; cvt.u32.u64 %0, t; }" : "=r"(a) : "l"(p));
    return a;
}
__device__ __forceinline__ void ldsm4(uint32_t* r, uint32_t addr) {
    asm volatile("ldmatrix.sync.aligned.m8n8.x4.shared.b16 {%0,%1,%2,%3}, [%4];"
        : "=r"(r[0]), "=r"(r[1]), "=r"(r[2]), "=r"(r[3]) : "r"(addr));
}
__device__ __forceinline__ void mma_bf16(float* d, const uint32_t* a, const uint32_t* b) {
    asm volatile("mma.sync.aligned.m16n8k16.row.col.f32.bf16.bf16.f32 "
        "{%0,%1,%2,%3}, {%4,%5,%6,%7}, {%8,%9}, {%0,%1,%2,%3};"
        : "+f"(d[0]), "+f"(d[1]), "+f"(d[2]), "+f"(d[3])
        : "r"(a[0]), "r"(a[1]), "r"(a[2]), "r"(a[3]), "r"(b[0]), "r"(b[1]));
}
__device__ __forceinline__ void cpa16(uint32_t dst, const void* src) {
    asm volatile("cp.async.cg.shared.global [%0], [%1], 16;" :: "r"(dst), "l"(src));
}
#define CP_COMMIT() asm volatile("cp.async.commit_group;" ::: "memory")
#define CP_WAIT1()  asm volatile("cp.async.wait_group 1;" ::: "memory")
#define CP_WAIT0()  asm volatile("cp.async.wait_group 0;" ::: "memory")

// ---------------------------------------------------------------------------
// GEMM core: C[128x128] = A[128xK] * B[128xK]^T with bf16 hi/lo 3-term split.
// SMEM per stage (double-buffered): Ahi|Alo|Bhi|Blo, each 128 rows x 32 bf16,
// rows padded to 80 B (conflict-free ldmatrix). Stage = 40960 B, total 81920 B.
// 256 threads = 8 warps (wm in 0..1 -> m 64, wn in 0..3 -> n 32).
// acc[mf][nf][4]: mf 0..3 (m16), nf 0..3 (n8).
// ---------------------------------------------------------------------------
#define GSTAGE 40960
#define GSMEM  (2*GSTAGE)
#define NSTG   (GK/32)

__device__ __forceinline__ void gemm_core(
    float acc[4][4][4], char* smem,
    const __nv_bfloat16* __restrict__ Ahi, const __nv_bfloat16* __restrict__ Alo,
    const __nv_bfloat16* __restrict__ Bhi, const __nv_bfloat16* __restrict__ Blo)
{
    const int tid = threadIdx.x, lane = tid & 31, wid = tid >> 5;
    const int wm = wid >> 2, wn = wid & 3;
    const uint32_t sb = smem_u32(smem);

#pragma unroll
    for (int i = 0; i < 4; i++)
#pragma unroll
        for (int j = 0; j < 4; j++)
#pragma unroll
            for (int v = 0; v < 4; v++) acc[i][j][v] = 0.f;

    // ldmatrix lane address components
    const int laneA_row = (lane & 7) + ((lane >> 3) & 1) * 8;
    const int laneA_kb  = (lane >> 4) * 16;
    const int laneB_row = (lane & 7) + (lane >> 4) * 8;
    const int laneB_kb  = ((lane >> 3) & 1) * 16;
    const uint32_t aB0 = sb + (uint32_t)(wm * 64 + laneA_row) * 80 + laneA_kb;
    const uint32_t bB0 = sb + 20480u + (uint32_t)(wn * 32 + laneB_row) * 80 + laneB_kb;

    // cp.async mapping: thread handles rows (tid>>2) and (tid>>2)+64, seg tid&3
    const int lrow = tid >> 2, lseg = tid & 3;
    const uint32_t dst0 = sb + (uint32_t)lrow * 80 + lseg * 16;

    auto load_stage = [&](int s) {
        const uint32_t d = dst0 + (uint32_t)(s & 1) * GSTAGE;
        const size_t go  = (size_t)lrow * GK + (size_t)s * 32 + lseg * 8;
        const size_t go2 = go + (size_t)64 * GK;
        cpa16(d,                  Ahi + go);
        cpa16(d + 64*80,          Ahi + go2);
        cpa16(d + 10240,          Alo + go);
        cpa16(d + 10240 + 64*80,  Alo + go2);
        cpa16(d + 20480,          Bhi + go);
        cpa16(d + 20480 + 64*80,  Bhi + go2);
        cpa16(d + 30720,          Blo + go);
        cpa16(d + 30720 + 64*80,  Blo + go2);
        CP_COMMIT();
    };

    load_stage(0);

    for (int s = 0; s < NSTG; s++) {
        if (s + 1 < NSTG) { load_stage(s + 1); CP_WAIT1(); }
        else              { CP_WAIT0(); }
        __syncthreads();

        const uint32_t aB = aB0 + (uint32_t)(s & 1) * GSTAGE;
        const uint32_t bB = bB0 + (uint32_t)(s & 1) * GSTAGE;
#pragma unroll
        for (int kk = 0; kk < 2; kk++) {
            const uint32_t ko = kk * 32;   // 16 bf16 = 32 B
            uint32_t ah[4][4], al[4][4], bh[2][4], bl[2][4];
#pragma unroll
            for (int mf = 0; mf < 4; mf++) {
                ldsm4(ah[mf], aB + mf * 1280 + ko);
                ldsm4(al[mf], aB + 10240 + mf * 1280 + ko);
            }
#pragma unroll
            for (int p = 0; p < 2; p++) {
                ldsm4(bh[p], bB + p * 1280 + ko);
                ldsm4(bl[p], bB + 10240 + p * 1280 + ko);
            }
#pragma unroll
            for (int mf = 0; mf < 4; mf++)
#pragma unroll
                for (int nf = 0; nf < 4; nf++) {
                    uint32_t* ph = &bh[nf >> 1][(nf & 1) * 2];
                    uint32_t* pl = &bl[nf >> 1][(nf & 1) * 2];
                    mma_bf16(acc[mf][nf], ah[mf], ph);   // hi*hi
                    mma_bf16(acc[mf][nf], al[mf], ph);   // lo*hi
                    mma_bf16(acc[mf][nf], ah[mf], pl);   // hi*lo
                }
        }
        __syncthreads();
    }
}

// ---------------------------------------------------------------------------
// GEMM A: fused QKV. grid (8, 64, 3) x 256. Scatter to [B,H,T,HD] fp32 + bias.
// ---------------------------------------------------------------------------
__global__ __launch_bounds__(256, 1)
void qkv_mma_kernel(const float* __restrict__ bk, const float* __restrict__ bq,
                    const float* __restrict__ bv)
{
    extern __shared__ char smem[];
    const int z = blockIdx.z;
    const float* bias; float* out;
    if (z == 0)      { bias = bk; out = g_k; }
    else if (z == 1) { bias = bq; out = g_q; }
    else             { bias = bv; out = g_v; }

    const int mBase = blockIdx.y << 7;
    const int nBase = blockIdx.x << 7;

    float acc[4][4][4];
    gemm_core(acc, smem,
        g_xhi + (size_t)mBase * GK, g_xlo + (size_t)mBase * GK,
        g_whi + (size_t)z * CC * CC + (size_t)nBase * GK,
        g_wlo + (size_t)z * CC * CC + (size_t)nBase * GK);

    const int lane = threadIdx.x & 31, wid = threadIdx.x >> 5;
    const int wm = wid >> 2, wn = wid & 3;
    const int er = lane >> 2, ec = (lane & 3) * 2;
#pragma unroll
    for (int mf = 0; mf < 4; mf++)
#pragma unroll
        for (int nf = 0; nf < 4; nf++)
#pragma unroll
            for (int hh = 0; hh < 2; hh++) {
                const int m = mBase + wm*64 + mf*16 + er + hh*8;
                const int n = nBase + wn*32 + nf*8 + ec;
                const int bb = m >> 11, t = m & (TT - 1);
                const int hd = n >> 6, d = n & 63;
                float2 o;
                o.x = acc[mf][nf][hh*2+0] + bias[n];
                o.y = acc[mf][nf][hh*2+1] + bias[n+1];
                *(float2*)&out[(((size_t)bb*HH + hd)*TT + t)*HD + d] = o;
            }
}

// ---------------------------------------------------------------------------
// GEMM B: output projection. grid (8, 64) x 256. Writes d_out + bias.
// ---------------------------------------------------------------------------
__global__ __launch_bounds__(256, 1)
void proj_mma_kernel(const float* __restrict__ bp, float* __restrict__ outp)
{
    extern __shared__ char smem[];
    const int mBase = blockIdx.y << 7;
    const int nBase = blockIdx.x << 7;

    float acc[4][4][4];
    gemm_core(acc, smem,
        g_yhi + (size_t)mBase * GK, g_ylo + (size_t)mBase * GK,
        g_whi + (size_t)3 * CC * CC + (size_t)nBase * GK,
        g_wlo + (size_t)3 * CC * CC + (size_t)nBase * GK);

    const int lane = threadIdx.x & 31, wid = threadIdx.x >> 5;
    const int wm = wid >> 2, wn = wid & 3;
    const int er = lane >> 2, ec = (lane & 3) * 2;
#pragma unroll
    for (int mf = 0; mf < 4; mf++)
#pragma unroll
        for (int nf = 0; nf < 4; nf++)
#pragma unroll
            for (int hh = 0; hh < 2; hh++) {
                const int m = mBase + wm*64 + mf*16 + er + hh*8;
                const int n = nBase + wn*32 + nf*8 + ec;
                float2 o;
                o.x = acc[mf][nf][hh*2+0] + bp[n];
                o.y = acc[mf][nf][hh*2+1] + bp[n+1];
                *(float2*)&outp[(size_t)m * CC + n] = o;
            }
}

// ---------------------------------------------------------------------------
// fp32 -> bf16 hi/lo split
// ---------------------------------------------------------------------------
__global__ __launch_bounds__(256)
void split_kernel(const float* __restrict__ src, __nv_bfloat16* __restrict__ hi,
                  __nv_bfloat16* __restrict__ lo, int n4)
{
    int i = blockIdx.x * blockDim.x + threadIdx.x;
    if (i >= n4) return;
    float4 v = ((const float4*)src)[i];
    __nv_bfloat16 h0 = __float2bfloat16(v.x), h1 = __float2bfloat16(v.y);
    __nv_bfloat16 h2 = __float2bfloat16(v.z), h3 = __float2bfloat16(v.w);
    __nv_bfloat16 l0 = __float2bfloat16(v.x - __bfloat162float(h0));
    __nv_bfloat16 l1 = __float2bfloat16(v.y - __bfloat162float(h1));
    __nv_bfloat16 l2 = __float2bfloat16(v.z - __bfloat162float(h2));
    __nv_bfloat16 l3 = __float2bfloat16(v.w - __bfloat162float(h3));
    __nv_bfloat162* H = (__nv_bfloat162*)hi;
    __nv_bfloat162* L = (__nv_bfloat162*)lo;
    H[2*i]   = __halves2bfloat162(h0, h1);
    H[2*i+1] = __halves2bfloat162(h2, h3);
    L[2*i]   = __halves2bfloat162(l0, l1);
    L[2*i+1] = __halves2bfloat162(l2, l3);
}

__global__ __launch_bounds__(256)
void split_w_kernel(const float* __restrict__ Wk, const float* __restrict__ Wq,
                    const float* __restrict__ Wv, const float* __restrict__ Wp)
{
    const int z = blockIdx.z;
    const float* src = (z == 0) ? Wk : (z == 1) ? Wq : (z == 2) ? Wv : Wp;
    __nv_bfloat16* hi = g_whi + (size_t)z * CC * CC;
    __nv_bfloat16* lo = g_wlo + (size_t)z * CC * CC;
    int i = blockIdx.x * blockDim.x + threadIdx.x;
    const int n4 = CC * CC / 4;
    if (i >= n4) return;
    float4 v = ((const float4*)src)[i];
    __nv_bfloat16 h0 = __float2bfloat16(v.x), h1 = __float2bfloat16(v.y);
    __nv_bfloat16 h2 = __float2bfloat16(v.z), h3 = __float2bfloat16(v.w);
    __nv_bfloat16 l0 = __float2bfloat16(v.x - __bfloat162float(h0));
    __nv_bfloat16 l1 = __float2bfloat16(v.y - __bfloat162float(h1));
    __nv_bfloat16 l2 = __float2bfloat16(v.z - __bfloat162float(h2));
    __nv_bfloat16 l3 = __float2bfloat16(v.w - __bfloat162float(h3));
    __nv_bfloat162* H = (__nv_bfloat162*)hi;
    __nv_bfloat162* L = (__nv_bfloat162*)lo;
    H[2*i]   = __halves2bfloat162(h0, h1);
    H[2*i+1] = __halves2bfloat162(h2, h3);
    L[2*i]   = __halves2bfloat162(l0, l1);
    L[2*i+1] = __halves2bfloat162(l2, l3);
}

// ---------------------------------------------------------------------------
// Causal flash attention (fp32 SIMT; epilogue writes bf16 hi/lo of y)
// ---------------------------------------------------------------------------
__global__ __launch_bounds__(256)
void flash_attn_kernel()
{
    extern __shared__ float sm[];
    float* Qs = sm;
    float* Ks = sm + 64*64;
    float* Vs = Ks + 64*65;
    float* Ps = Vs + 64*64;

    const int tid = threadIdx.x;
    const int ty = tid >> 4, tx = tid & 15;
    const int r0 = ty << 2, c0 = tx << 2;
    const int qt = blockIdx.x;
    const int bh = blockIdx.y;

    const float* Qg = g_q + (size_t)bh * TT * HD + (size_t)qt * 64 * HD;
    const float* Kg = g_k + (size_t)bh * TT * HD;
    const float* Vg = g_v + (size_t)bh * TT * HD;

    {
        int row = tid >> 4;
        int c4  = (tid & 15) << 2;
#pragma unroll
        for (int it = 0; it < 4; it++) {
            int r = row + it*16;
            float4 v = *(const float4*)&Qg[(size_t)r*HD + c4];
            v.x *= 0.125f; v.y *= 0.125f; v.z *= 0.125f; v.w *= 0.125f;
            *(float4*)&Qs[r*64 + c4] = v;
        }
    }

    float m_i[4], l_i[4], O[4][4];
#pragma unroll
    for (int i = 0; i < 4; i++) {
        m_i[i] = -INFINITY; l_i[i] = 0.f;
#pragma unroll
        for (int j = 0; j < 4; j++) O[i][j] = 0.f;
    }

    for (int kt = 0; kt <= qt; kt++) {
        __syncthreads();
        {
            int row = tid >> 4;
            int c4  = (tid & 15) << 2;
#pragma unroll
            for (int it = 0; it < 4; it++) {
                int r = row + it*16;
                size_t goff = (size_t)(kt*64 + r) * HD + c4;
                float4 kv = *(const float4*)&Kg[goff];
                Ks[r*65 + c4+0] = kv.x; Ks[r*65 + c4+1] = kv.y;
                Ks[r*65 + c4+2] = kv.z; Ks[r*65 + c4+3] = kv.w;
                float4 vv = *(const float4*)&Vg[goff];
                *(float4*)&Vs[r*64 + c4] = vv;
            }
        }
        __syncthreads();

        float S[4][4];
#pragma unroll
        for (int i = 0; i < 4; i++)
#pragma unroll
            for (int j = 0; j < 4; j++) S[i][j] = 0.f;
#pragma unroll 8
        for (int d = 0; d < 64; d++) {
            float qv[4], kv[4];
#pragma unroll
            for (int i = 0; i < 4; i++) qv[i] = Qs[(r0+i)*64 + d];
#pragma unroll
            for (int j = 0; j < 4; j++) kv[j] = Ks[(c0+j)*65 + d];
#pragma unroll
            for (int i = 0; i < 4; i++)
#pragma unroll
                for (int j = 0; j < 4; j++)
                    S[i][j] = fmaf(qv[i], kv[j], S[i][j]);
        }

        if (kt == qt) {
#pragma unroll
            for (int i = 0; i < 4; i++)
#pragma unroll
                for (int j = 0; j < 4; j++)
                    if (c0 + j > r0 + i) S[i][j] = -INFINITY;
        }

        float mloc[4];
#pragma unroll
        for (int i = 0; i < 4; i++)
            mloc[i] = fmaxf(fmaxf(S[i][0], S[i][1]), fmaxf(S[i][2], S[i][3]));
#pragma unroll
        for (int off = 1; off < 16; off <<= 1)
#pragma unroll
            for (int i = 0; i < 4; i++)
                mloc[i] = fmaxf(mloc[i], __shfl_xor_sync(0xffffffffu, mloc[i], off));

        float corr[4], rs[4];
#pragma unroll
        for (int i = 0; i < 4; i++) {
            float mn = fmaxf(m_i[i], mloc[i]);
            corr[i] = __expf(m_i[i] - mn);
            m_i[i] = mn;
        }
#pragma unroll
        for (int i = 0; i < 4; i++) {
            float s = 0.f;
#pragma unroll
            for (int j = 0; j < 4; j++) {
                float p = __expf(S[i][j] - m_i[i]);
                S[i][j] = p;
                s += p;
            }
            rs[i] = s;
        }
#pragma unroll
        for (int off = 1; off < 16; off <<= 1)
#pragma unroll
            for (int i = 0; i < 4; i++)
                rs[i] += __shfl_xor_sync(0xffffffffu, rs[i], off);
#pragma unroll
        for (int i = 0; i < 4; i++) {
            l_i[i] = l_i[i] * corr[i] + rs[i];
#pragma unroll
            for (int j = 0; j < 4; j++) O[i][j] *= corr[i];
        }

#pragma unroll
        for (int i = 0; i < 4; i++)
#pragma unroll
            for (int j = 0; j < 4; j++)
                Ps[(r0+i)*65 + c0 + j] = S[i][j];
        __syncthreads();

#pragma unroll 8
        for (int c = 0; c < 64; c++) {
            float pv[4], vv[4];
#pragma unroll
            for (int i = 0; i < 4; i++) pv[i] = Ps[(r0+i)*65 + c];
#pragma unroll
            for (int j = 0; j < 4; j++) vv[j] = Vs[c*64 + c0 + j];
#pragma unroll
            for (int i = 0; i < 4; i++)
#pragma unroll
                for (int j = 0; j < 4; j++)
                    O[i][j] = fmaf(pv[i], vv[j], O[i][j]);
        }
    }

    const int b = bh >> 4, h = bh & 15;
#pragma unroll
    for (int i = 0; i < 4; i++) {
        float inv = 1.0f / l_i[i];
        int t = qt*64 + r0 + i;
        size_t base = ((size_t)b*TT + t)*CC + h*HD + c0;
        float y0 = O[i][0]*inv, y1 = O[i][1]*inv, y2 = O[i][2]*inv, y3 = O[i][3]*inv;
        __nv_bfloat16 h0 = __float2bfloat16(y0), h1 = __float2bfloat16(y1);
        __nv_bfloat16 h2 = __float2bfloat16(y2), h3 = __float2bfloat16(y3);
        __nv_bfloat16 l0 = __float2bfloat16(y0 - __bfloat162float(h0));
        __nv_bfloat16 l1 = __float2bfloat16(y1 - __bfloat162float(h1));
        __nv_bfloat16 l2 = __float2bfloat16(y2 - __bfloat162float(h2));
        __nv_bfloat16 l3 = __float2bfloat16(y3 - __bfloat162float(h3));
        *(__nv_bfloat162*)&g_yhi[base]   = __halves2bfloat162(h0, h1);
        *(__nv_bfloat162*)&g_yhi[base+2] = __halves2bfloat162(h2, h3);
        *(__nv_bfloat162*)&g_ylo[base]   = __halves2bfloat162(l0, l1);
        *(__nv_bfloat162*)&g_ylo[base+2] = __halves2bfloat162(l2, l3);
    }
}

// ---------------------------------------------------------------------------
extern "C" void kernel_launch(void* const* d_in, const int* in_sizes, int n_in,
                              void* d_out, int out_size)
{
    const float* x  = (const float*)d_in[0];
    const float* Wk = (const float*)d_in[1];
    const float* bk = (const float*)d_in[2];
    const float* Wq = (const float*)d_in[3];
    const float* bq = (const float*)d_in[4];
    const float* Wv = (const float*)d_in[5];
    const float* bv = (const float*)d_in[6];
    const float* Wp = (const float*)d_in[7];
    const float* bp = (const float*)d_in[8];
    float* outp = (float*)d_out;

    cudaFuncSetAttribute((const void*)flash_attn_kernel,
                         cudaFuncAttributeMaxDynamicSharedMemorySize, 66048);
    cudaFuncSetAttribute((const void*)qkv_mma_kernel,
                         cudaFuncAttributeMaxDynamicSharedMemorySize, GSMEM);
    cudaFuncSetAttribute((const void*)proj_mma_kernel,
                         cudaFuncAttributeMaxDynamicSharedMemorySize, GSMEM);

    // 1. Split X and weights into bf16 hi/lo
    {
        __nv_bfloat16 *xhi, *xlo;
        cudaGetSymbolAddress((void**)&xhi, g_xhi);
        cudaGetSymbolAddress((void**)&xlo, g_xlo);
        const int n4 = BB * TT * CC / 4;
        split_kernel<<<(n4 + 255) / 256, 256>>>(x, xhi, xlo, n4);
    }
    split_w_kernel<<<dim3((CC*CC/4 + 255)/256, 1, 4), 256>>>(Wk, Wq, Wv, Wp);

    // 2. QKV projections (HMMA split-3), scatter + bias
    qkv_mma_kernel<<<dim3(8, 64, 3), 256, GSMEM>>>(bk, bq, bv);

    // 3. Causal flash attention (fp32), writes bf16 split of y
    flash_attn_kernel<<<dim3(32, 64), 256, 66048>>>();

    // 4. Output projection (HMMA split-3), bias, d_out
    proj_mma_kernel<<<dim3(8, 64), 256, GSMEM>>>(bp, outp);
}